// round 17
// baseline (speedup 1.0000x reference)
#include <cuda_runtime.h>
#include <cuda_fp16.h>
#include <cstdint>

#define NPTS 1000000
#define WRES 64
#define NBUCK 4096

// Staging: transposed grids fp16 [3,H,64,16], offsets {0,393216,1179648,2752512}
__device__ __align__(16) __half g_stage[5898240];
// 4-corner 128B blocks (see R14 swizzle), offsets {0,1572864,4718592,11010048}
__device__ __align__(16) __half g_dup[23592960];
// sort scratch
__device__ int g_hist[NBUCK];
__device__ int g_off[NBUCK];
__device__ int g_sidx[NPTS];

__device__ __forceinline__ uint4 ldg_pol(const void* p, uint64_t policy) {
    uint4 v;
    asm("ld.global.nc.L2::cache_hint.v4.u32 {%0,%1,%2,%3}, [%4], %5;"
        : "=r"(v.x), "=r"(v.y), "=r"(v.z), "=r"(v.w) : "l"(p), "l"(policy));
    return v;
}

// ---- pass 1: transpose [3,16,H,64] fp32 -> [3,H,64,16] fp16 ----
__global__ void __launch_bounds__(256) stage_k(const float* __restrict__ g0,
                                               const float* __restrict__ g1,
                                               const float* __restrict__ g2,
                                               const float* __restrict__ g3) {
    int idx = blockIdx.x * blockDim.x + threadIdx.x;
    if (idx >= 368640) return;
    const float* g;
    int H, toff, local, hshift;
    if (idx < 24576)       { g = g0; H = 128;  toff = 0;       local = idx;          hshift = 7;  }
    else if (idx < 73728)  { g = g1; H = 256;  toff = 393216;  local = idx - 24576;  hshift = 8;  }
    else if (idx < 172032) { g = g2; H = 512;  toff = 1179648; local = idx - 73728;  hshift = 9;  }
    else                   { g = g3; H = 1024; toff = 2752512; local = idx - 172032; hshift = 10; }
    int w = local & 63;
    int rest = local >> 6;
    int h = rest & (H - 1);
    int ci = rest >> hshift;
    const float* src = g + ((size_t)(ci * 16) * H + h) * WRES + w;
    float tmp[16];
    size_t fstride = (size_t)H * WRES;
#pragma unroll
    for (int f = 0; f < 16; f++) tmp[f] = __ldcs(&src[f * fstride]);
    __half2 hv[8];
#pragma unroll
    for (int f = 0; f < 8; f++) hv[f] = __floats2half2_rn(tmp[2 * f], tmp[2 * f + 1]);
    uint4* dst = reinterpret_cast<uint4*>(g_stage + toff + (size_t)local * 16);
    const uint32_t* u = reinterpret_cast<const uint32_t*>(hv);
    dst[0] = make_uint4(u[0], u[1], u[2], u[3]);
    dst[1] = make_uint4(u[4], u[5], u[6], u[7]);
}

// ---- pass 2: build 128B 4-corner swizzled blocks from staging ----
__global__ void __launch_bounds__(256) blocks_k() {
    int idx = blockIdx.x * blockDim.x + threadIdx.x;
    if (idx >= 368640) return;
    int H, soff, doff, local, hshift;
    if (idx < 24576)       { H = 128;  soff = 0;       doff = 0;        local = idx;          hshift = 7;  }
    else if (idx < 73728)  { H = 256;  soff = 393216;  doff = 1572864;  local = idx - 24576;  hshift = 8;  }
    else if (idx < 172032) { H = 512;  soff = 1179648; doff = 4718592;  local = idx - 73728;  hshift = 9;  }
    else                   { H = 1024; soff = 2752512; doff = 11010048; local = idx - 172032; hshift = 10; }
    int x = local & 63;
    int rest = local >> 6;
    int y = rest & (H - 1);
    (void)hshift;

    const __half* base = g_stage + soff + (size_t)local * 16;
    int dx = (x < 63) ? 16 : 0;      // halfs to texel x+1
    int dy = (y < H - 1) ? 1024 : 0; // halfs to texel row y+1

    // load 4 texels as half2[8] each
    __half2 T[2][2][8];
#pragma unroll
    for (int xp = 0; xp < 2; xp++)
#pragma unroll
        for (int yp = 0; yp < 2; yp++) {
            const uint4* p = reinterpret_cast<const uint4*>(base + xp * dx + yp * dy);
            uint4 a = p[0], b = p[1];
            uint32_t uu[8] = {a.x, a.y, a.z, a.w, b.x, b.y, b.z, b.w};
#pragma unroll
            for (int k = 0; k < 8; k++) T[xp][yp][k] = *reinterpret_cast<__half2*>(&uu[k]);
        }

    __half* dst = g_dup + doff + (size_t)local * 64;
#pragma unroll
    for (int c = 0; c < 8; c++) {
        int h  = c >> 2;
        int xp = (c >> 1) & 1;
        int yp = c & 1;
        __half2 e0 = T[xp][yp][h * 4 + xp * 2 + yp];
        __half2 e1 = T[xp][yp][h * 4 + xp * 2 + 1 - yp];
        __half2 e2 = T[xp][yp][h * 4 + 2 - 2 * xp + yp];
        __half2 e3 = T[xp][yp][h * 4 + 3 - 2 * xp - yp];
        uint4 u;
        u.x = *(uint32_t*)&e0; u.y = *(uint32_t*)&e1;
        u.z = *(uint32_t*)&e2; u.w = *(uint32_t*)&e3;
        *reinterpret_cast<uint4*>(dst + c * 8) = u;
    }
}

// ---- sort: zero hist, histogram, scan, scatter ----
__device__ __forceinline__ int bucket_of(float r) {
    int q = (int)((r + 1.0f) * 2048.0f);
    return min(max(q, 0), NBUCK - 1);
}

__global__ void zhist_k() {
    int i = blockIdx.x * blockDim.x + threadIdx.x;
    if (i < NBUCK) g_hist[i] = 0;
}

__global__ void hist_k(const float* __restrict__ radius) {
    int n = blockIdx.x * blockDim.x + threadIdx.x;
    if (n >= NPTS) return;
    atomicAdd(&g_hist[bucket_of(radius[n])], 1);
}

__global__ void __launch_bounds__(1024) scan_k() {
    __shared__ int wsum[32];
    int tid = threadIdx.x;
    int a0 = g_hist[tid * 4 + 0];
    int a1 = g_hist[tid * 4 + 1];
    int a2 = g_hist[tid * 4 + 2];
    int a3 = g_hist[tid * 4 + 3];
    int ts = a0 + a1 + a2 + a3;
    int lane = tid & 31, wid = tid >> 5;
    int v = ts;
#pragma unroll
    for (int d = 1; d < 32; d <<= 1) {
        int u = __shfl_up_sync(0xffffffffu, v, d);
        if (lane >= d) v += u;
    }
    if (lane == 31) wsum[wid] = v;
    __syncthreads();
    if (wid == 0) {
        int s = wsum[lane];
        int w = s;
#pragma unroll
        for (int d = 1; d < 32; d <<= 1) {
            int u = __shfl_up_sync(0xffffffffu, w, d);
            if (lane >= d) w += u;
        }
        wsum[lane] = w - s;   // exclusive warp offsets
    }
    __syncthreads();
    int texcl = wsum[wid] + (v - ts);
    g_off[tid * 4 + 0] = texcl;
    g_off[tid * 4 + 1] = texcl + a0;
    g_off[tid * 4 + 2] = texcl + a0 + a1;
    g_off[tid * 4 + 3] = texcl + a0 + a1 + a2;
}

__global__ void scat_k(const float* __restrict__ radius) {
    int n = blockIdx.x * blockDim.x + threadIdx.x;
    if (n >= NPTS) return;
    int pos = atomicAdd(&g_off[bucket_of(radius[n])], 1);
    g_sidx[pos] = n;
}

// ---- main sampler: 8 lanes per point (sorted order), 12 samples/group ----
// lane r = (h<<2)|(xc<<1)|yc; one LDG.128 per (ci,scale) covers the 128B block.
__global__ void __launch_bounds__(512) sample_k(const float* __restrict__ pts,
                                                const float* __restrict__ radius,
                                                float* __restrict__ out) {
    int t = blockIdx.x * blockDim.x + threadIdx.x;
    int pos = t >> 3;             // 1M points exactly
    int r = t & 7;
    int n = g_sidx[pos];

    uint64_t pol;
    asm("createpolicy.fractional.L2::evict_last.b64 %0, 1.0;" : "=l"(pol));

    float yv = __ldg(radius + n);
    float yp1 = yv + 1.0f;

    // shared y setup per scale
    int y0s[4];
    float wyr_s[4];
#pragma unroll
    for (int s = 0; s < 4; s++) {
        int H = 128 << s;
        float fy = yp1 * (0.5f * (float)(H - 1));
        float y0f = floorf(fy);
        float wy = fy - y0f;
        y0s[s] = min(max((int)y0f, 0), H - 1);
        wyr_s[s] = (r & 1) ? wy : (1.0f - wy);
    }

    const int doffs[4] = {0, 1572864, 4718592, 11010048};
    float* obase = out + (size_t)n * 192 + r * 2;

#pragma unroll
    for (int ci = 0; ci < 3; ci++) {
        float xv = __ldg(pts + n * 3 + ci);
        float fx = (xv + 1.0f) * 31.5f;
        float x0f = floorf(fx);
        float wx = fx - x0f;
        int x0 = min(max((int)x0f, 0), 63);
        float wxr = (r & 2) ? wx : (1.0f - wx);

        uint4 v[4];
#pragma unroll
        for (int s = 0; s < 4; s++) {
            int H = 128 << s;
            const __half* b = g_dup + doffs[s] +
                ((size_t)(ci * H + y0s[s]) * 64 + x0) * 64 + r * 8;
            v[s] = ldg_pol(b, pol);
        }

#pragma unroll
        for (int s = 0; s < 4; s++) {
            float wf = wxr * wyr_s[s];
            const __half2* a = reinterpret_cast<const __half2*>(&v[s]);
            float2 f01 = __half22float2(a[0]);
            float2 f23 = __half22float2(a[1]);
            __half2 wh2 = __float2half2_rn(wf);
            __half2 s2 = __hmul2(a[2], wh2);
            __half2 s3 = __hmul2(a[3], wh2);
            uint32_t u2 = __shfl_xor_sync(0xffffffffu, *(uint32_t*)&s2, 2);
            uint32_t u3 = __shfl_xor_sync(0xffffffffu, *(uint32_t*)&s3, 2);
            float2 g01 = __half22float2(*(__half2*)&u2);
            float2 g23 = __half22float2(*(__half2*)&u3);
            float k0 = f01.x * wf + g01.x;
            float k1 = f01.y * wf + g01.y;
            float k2 = f23.x * wf + g23.x;
            float k3 = f23.y * wf + g23.y;
            float r2 = __shfl_xor_sync(0xffffffffu, k2, 1);
            float r3 = __shfl_xor_sync(0xffffffffu, k3, 1);
            __stcs(reinterpret_cast<float2*>(obase + ci * 16 + s * 48),
                   make_float2(k0 + r2, k1 + r3));
        }
    }
}

extern "C" void kernel_launch(void* const* d_in, const int* in_sizes, int n_in,
                              void* d_out, int out_size) {
    const float* pts    = (const float*)d_in[0];
    const float* radius = (const float*)d_in[1];
    float* out = (float*)d_out;

    stage_k<<<1440, 256>>>((const float*)d_in[2], (const float*)d_in[3],
                           (const float*)d_in[4], (const float*)d_in[5]);
    blocks_k<<<1440, 256>>>();

    zhist_k<<<16, 256>>>();
    hist_k<<<3907, 256>>>(radius);
    scan_k<<<1, 1024>>>();
    scat_k<<<3907, 256>>>(radius);

    // 1M points * 8 lanes = 8M threads; 512/block -> 15625 blocks exactly
    sample_k<<<15625, 512>>>(pts, radius, out);
}